// round 13
// baseline (speedup 1.0000x reference)
#include <cuda_runtime.h>
#include <cstdint>

#define S 8192
#define H 1024
#define NSM 128
#define NWORK 24            // GEMM worker CTAs on spare SMs (GB300: 152 SMs)
#define SCAN_THREADS 544    // 16 dot-warps + finalizer warp 16 (highest wid)
#define NREP 8              // packet-line replicas (absorbs pipelined poll)
#define NTILE_N 24          // 3072 / 128
#define NTILE_M 64          // 8192 / 128
#define NTILES (NTILE_M * NTILE_N)

// Scratch: input-side gate projections gx[S][3H].
__device__ float g_gx[(size_t)S * 3 * H];
// h-exchange lines, replicated x8 and double buffered:
//   [rep][slot][producer][32 floats] = one 128B line per (rep,slot,producer).
// Three self-validating 16B packets per line:
//   [tag h0 h1 h2] [tag h3 h4 h5] [tag h6 h7 pad]  (tag = step+1 as uint bits)
__device__ __align__(128) float g_hline[NREP * 2 * NSM * 32];
// per-m-block gx completion counters, padded to one 128B line each
__device__ __align__(128) unsigned int g_gxready[NTILE_M * 32];
// work-stealing tile counter for the GEMM workers
__device__ unsigned int g_tilectr;

// ---------------------------------------------------------------------------
// packed fp32x2 helpers (sm_103a FFMA2 path)
// ---------------------------------------------------------------------------
__device__ __forceinline__ unsigned long long pack2(float lo, float hi) {
    unsigned long long r;
    asm("mov.b64 %0, {%1, %2};" : "=l"(r) : "f"(lo), "f"(hi));
    return r;
}
__device__ __forceinline__ unsigned long long ffma2(unsigned long long a,
                                                    unsigned long long b,
                                                    unsigned long long c) {
    unsigned long long d;
    asm("fma.rn.f32x2 %0, %1, %2, %3;" : "=l"(d) : "l"(a), "l"(b), "l"(c));
    return d;
}
__device__ __forceinline__ float hsum2(unsigned long long a) {
    float lo, hi;
    asm("mov.b64 {%0, %1}, %2;" : "=f"(lo), "=f"(hi) : "l"(a));
    return lo + hi;
}

// ---------------------------------------------------------------------------
// Kernel 1: clear exchange state for this graph replay (runs first, tiny).
// ---------------------------------------------------------------------------
__global__ void clear_kernel() {
    int idx = blockIdx.x * blockDim.x + threadIdx.x;   // 32*256 = 8192
    float4 z = make_float4(0.f, 0.f, 0.f, 0.f);
    ((float4*)g_hline)[idx] = z;                       // 16384 float4 total
    ((float4*)g_hline)[idx + 8192] = z;
    if (idx < NTILE_M * 32) g_gxready[idx] = 0u;
    if (idx == 0) g_tilectr = 0u;
}

// ---------------------------------------------------------------------------
// Kernel 2 (fused): bids 0..127 = persistent GRU scan;
//                   bids 128..151 = persistent GEMM workers producing gx.
//
// Scan protocol (R13): self-validating 16B packets [tag|3 floats], NREP=8
// replicas (consumer CTA polls replica bid&7). Leader warps (chunk c=warp&3,
// g==0) run a 2-DEEP PIPELINED poll: two load batches in flight, halving
// the detection quantization; per-lane predicated accept. Leaders relay h
// via smem then bar.ARRIVE the chunk barrier (siblings bar.sync) and go
// straight to dots (h already in regs). Dot warps bar.ARRIVE(7) after
// writing partials and head directly into the next step's poll; only the
// finalizer bar.SYNCs(7). All reuse hazards are covered by the tag-gated
// cross-CTA skew<=1 property (remote t+1 publish implies this CTA's
// finalizer consumed partials(t) and siblings consumed s_h(t)).
// ---------------------------------------------------------------------------
__global__ __launch_bounds__(SCAN_THREADS, 1) void fused_kernel(
    const float* __restrict__ A,      // inp [S,1024]
    const float* __restrict__ Wih,    // [3072,1024]
    const float* __restrict__ bih,    // [3072]
    const float* __restrict__ Whh,    // [3072,1024]
    const float* __restrict__ bhh,    // [3072]
    float* __restrict__ out)          // [S,1024]
{
    const int tid  = threadIdx.x;
    const int warp = tid >> 5;
    const int lane = tid & 31;
    const int bid  = blockIdx.x;

    if (bid >= NSM) {
        // ================= GEMM worker: gx = inp @ Wih^T + bih =============
        __shared__ __align__(16) float As[16][132];
        __shared__ __align__(16) float Bs[16][132];
        __shared__ int s_tile;
        const bool act = (tid < 256);
        const int tx = tid & 15;
        const int ty = (tid >> 4) & 15;

        for (;;) {
            if (tid == 0) s_tile = (int)atomicAdd(&g_tilectr, 1u);
            __syncthreads();
            const int ti = s_tile;
            if (ti >= NTILES) break;
            const int mb = ti / NTILE_N;
            const int m0 = mb * 128;
            const int n0 = (ti - mb * NTILE_N) * 128;

            unsigned long long acc2[8][4];
#pragma unroll
            for (int i = 0; i < 8; ++i)
#pragma unroll
                for (int q = 0; q < 4; ++q) acc2[i][q] = 0ULL;

            for (int kt = 0; kt < 1024; kt += 16) {
                if (act) {
#pragma unroll
                    for (int r = 0; r < 2; ++r) {
                        int idx = tid + r * 256;
                        int row = idx >> 2;
                        int kq  = idx & 3;
                        float4 v = *(const float4*)(A + (size_t)(m0 + row) * 1024 + kt + kq * 4);
                        As[kq * 4 + 0][row] = v.x;
                        As[kq * 4 + 1][row] = v.y;
                        As[kq * 4 + 2][row] = v.z;
                        As[kq * 4 + 3][row] = v.w;
                    }
#pragma unroll
                    for (int r = 0; r < 2; ++r) {
                        int idx = tid + r * 256;
                        int n  = idx >> 2;
                        int kq = idx & 3;
                        float4 v = *(const float4*)(Wih + (size_t)(n0 + n) * 1024 + kt + kq * 4);
                        Bs[kq * 4 + 0][n] = v.x;
                        Bs[kq * 4 + 1][n] = v.y;
                        Bs[kq * 4 + 2][n] = v.z;
                        Bs[kq * 4 + 3][n] = v.w;
                    }
                }
                __syncthreads();
                if (act) {
#pragma unroll
                    for (int k = 0; k < 16; ++k) {
                        float4 b0 = *(const float4*)&Bs[k][tx * 8];
                        float4 b1 = *(const float4*)&Bs[k][tx * 8 + 4];
                        unsigned long long rb2[4];
                        rb2[0] = pack2(b0.x, b0.y);
                        rb2[1] = pack2(b0.z, b0.w);
                        rb2[2] = pack2(b1.x, b1.y);
                        rb2[3] = pack2(b1.z, b1.w);
#pragma unroll
                        for (int i = 0; i < 8; ++i) {
                            float a = As[k][ty * 8 + i];
                            unsigned long long a2 = pack2(a, a);
#pragma unroll
                            for (int q = 0; q < 4; ++q)
                                acc2[i][q] = ffma2(a2, rb2[q], acc2[i][q]);
                        }
                    }
                }
                __syncthreads();
            }

            if (act) {
#pragma unroll
                for (int i = 0; i < 8; ++i) {
                    size_t rowoff = (size_t)(m0 + ty * 8 + i) * 3072 + n0 + tx * 8;
#pragma unroll
                    for (int jq = 0; jq < 2; ++jq) {
                        float lo0, hi0, lo1, hi1;
                        asm("mov.b64 {%0, %1}, %2;" : "=f"(lo0), "=f"(hi0) : "l"(acc2[i][jq * 2 + 0]));
                        asm("mov.b64 {%0, %1}, %2;" : "=f"(lo1), "=f"(hi1) : "l"(acc2[i][jq * 2 + 1]));
                        float4 v;
                        v.x = lo0 + bih[n0 + tx * 8 + jq * 4 + 0];
                        v.y = hi0 + bih[n0 + tx * 8 + jq * 4 + 1];
                        v.z = lo1 + bih[n0 + tx * 8 + jq * 4 + 2];
                        v.w = hi1 + bih[n0 + tx * 8 + jq * 4 + 3];
                        *(float4*)(g_gx + rowoff + jq * 4) = v;
                    }
                }
            }
            __threadfence();     // make this thread's gx stores GPU-visible
            __syncthreads();     // all threads' fences done before the flag
            if (tid == 0) {
                asm volatile("red.release.gpu.global.add.u32 [%0], 1;"
                             :: "l"(&g_gxready[mb * 32]) : "memory");
            }
        }
        return;
    }

    // ==================== persistent GRU scan ==============================
    const int obase = bid * 8;

    __shared__ __align__(16) float s_h[4][256];        // per-chunk h relay
    __shared__ __align__(16) float partials[2][24][36];

    const bool isfin = (warp == 16);
    const int c = warp & 3;              // k-chunk (0..3): leaders on SMSP 0..3
    const int g = warp >> 2;             // row-group (0..3)
    const int k0 = c * 256 + lane * 8;
    const int p  = c * 32 + lane;        // producer this lane covers (g==0)
    const int myrep = bid & (NREP - 1);  // replica this CTA polls

    // ---- dot-warp setup: 6 gate-rows x 8 cols of W_hh, packed f32x2 ----
    unsigned long long w2[6][4];
    if (!isfin) {
#pragma unroll
        for (int j = 0; j < 6; ++j) {
            int gr  = g * 6 + j;                          // 0..23
            int row = (gr >> 3) * H + obase + (gr & 7);   // gate*H + out idx
            const float4* pw = (const float4*)(Whh + (size_t)row * H + k0);
            float4 a = pw[0], b = pw[1];
            w2[j][0] = pack2(a.x, a.y);
            w2[j][1] = pack2(a.z, a.w);
            w2[j][2] = pack2(b.x, b.y);
            w2[j][3] = pack2(b.z, b.w);
        }
    }

    // ---- finalizer setup ----
    const int o = lane & 7;
    float bh = 0.f;
    if (isfin && lane < 24) bh = bhh[(lane >> 3) * H + obase + o];
    float hprev = 0.f;                   // lanes 0..7 carry h for their dim
    const size_t gx_lane_off = (size_t)(lane >> 3) * H + obase + o;

#define POLL_ISSUE(R)                                                        \
    do {                                                                     \
        asm volatile("ld.volatile.global.v4.f32 {%0,%1,%2,%3}, [%4];"        \
            : "=f"(R[0]), "=f"(R[1]), "=f"(R[2]), "=f"(R[3]) : "l"(base));   \
        asm volatile("ld.volatile.global.v4.f32 {%0,%1,%2,%3}, [%4];"        \
            : "=f"(R[4]), "=f"(R[5]), "=f"(R[6]), "=f"(R[7])                 \
            : "l"(base + 4));                                                \
        asm volatile("ld.volatile.global.v4.f32 {%0,%1,%2,%3}, [%4];"        \
            : "=f"(R[8]), "=f"(R[9]), "=f"(R[10]), "=f"(R[11])               \
            : "l"(base + 8));                                                \
    } while (0)

#define POLL_TRY(R)                                                          \
    do {                                                                     \
        if (!ok && (__float_as_uint(R[0]) == want) &&                        \
                   (__float_as_uint(R[4]) == want) &&                        \
                   (__float_as_uint(R[8]) == want)) {                        \
            hv0 = R[1]; hv1 = R[2];  hv2 = R[3]; hv3 = R[5];                 \
            hv4 = R[6]; hv5 = R[7];  hv6 = R[9]; hv7 = R[10];                \
            ok = true;                                                       \
        }                                                                    \
    } while (0)

    for (int t = 0; t < S; ++t) {
        const int buf = t & 1;

        if (isfin) {
            // gate on gx availability once per m-block (128 steps)
            if ((t & 127) == 0) {
                const unsigned int* rp = &g_gxready[(t >> 7) * 32];
                unsigned int v;
                do {
                    asm volatile("ld.acquire.gpu.global.u32 %0, [%1];"
                                 : "=r"(v) : "l"(rp) : "memory");
                } while (v < (unsigned)NTILE_N);
            }
            // prefetch gx (L2, bypass L1 -- written by worker SMs)
            float gxv = 0.f;
            if (lane < 24)
                gxv = __ldcg(&g_gx[(size_t)t * (3 * H) + gx_lane_off]);

            // wait for all 16 dot warps' partials (they only arrive)
            asm volatile("bar.sync 7, %0;" :: "r"(SCAN_THREADS) : "memory");

            float s = 0.f;
            if (lane < 24) {
                const float4* pr = (const float4*)(&partials[buf][lane][0]);
                float4 p0 = pr[0], p1 = pr[1], p2 = pr[2], p3 = pr[3];
                float4 p4 = pr[4], p5 = pr[5], p6 = pr[6], p7 = pr[7];
                float4 q0, q1, q2, q3, r0, r1, f;
                q0.x = p0.x + p1.x; q0.y = p0.y + p1.y; q0.z = p0.z + p1.z; q0.w = p0.w + p1.w;
                q1.x = p2.x + p3.x; q1.y = p2.y + p3.y; q1.z = p2.z + p3.z; q1.w = p2.w + p3.w;
                q2.x = p4.x + p5.x; q2.y = p4.y + p5.y; q2.z = p4.z + p5.z; q2.w = p4.w + p5.w;
                q3.x = p6.x + p7.x; q3.y = p6.y + p7.y; q3.z = p6.z + p7.z; q3.w = p6.w + p7.w;
                r0.x = q0.x + q1.x; r0.y = q0.y + q1.y; r0.z = q0.z + q1.z; r0.w = q0.w + q1.w;
                r1.x = q2.x + q3.x; r1.y = q2.y + q3.y; r1.z = q2.z + q3.z; r1.w = q2.w + q3.w;
                f.x = r0.x + r1.x; f.y = r0.y + r1.y; f.z = r0.z + r1.z; f.w = r0.w + r1.w;
                s = bh + ((f.x + f.y) + (f.z + f.w));
            }
            float val = s + ((lane < 16) ? gxv : 0.f);
            float sig = __fdividef(1.f, 1.f + __expf(-val));  // 24 parallel
            float v_n  = __shfl_sync(0xFFFFFFFFu, s,   o + 16);
            float gx_n = __shfl_sync(0xFFFFFFFFu, gxv, o + 16);
            float zz   = __shfl_sync(0xFFFFFFFFu, sig, o + 8);
            float hn = 0.f;
            if (lane < 8) {
                float r  = sig;
                float a  = gx_n + r * v_n;
                float e2 = __expf(2.f * a);
                float n  = 1.f - __fdividef(2.f, e2 + 1.f);   // tanh(a)
                hn = zz * (hprev - n) + n;                    // (1-z)*n + z*h
                hprev = hn;
            }
            // ---- publish: 24 packets (3 per replica x 8), no fence ----
            {
                const unsigned tagv = (unsigned)(t + 1);
                const int j   = lane - (lane / 3) * 3;   // lane % 3
                const int rep = lane / 3;                // 0..7 for lane<24
                int s0 = (3 * j)     & 31;
                int s1 = (3 * j + 1) & 31;
                int s2 = (3 * j + 2) & 31;
                float x = __shfl_sync(0xFFFFFFFFu, hn, s0);
                float y = __shfl_sync(0xFFFFFFFFu, hn, s1);
                float z = __shfl_sync(0xFFFFFFFFu, hn, s2);
                if (lane < 24) {
                    float* dst = &g_hline[(((size_t)rep * 2 + buf) * NSM + bid)
                                          * 32 + j * 4];
                    asm volatile(
                        "st.volatile.global.v4.f32 [%0], {%1, %2, %3, %4};"
                        :: "l"(dst), "f"(__uint_as_float(tagv)),
                           "f"(x), "f"(y), "f"(z) : "memory");
                }
            }
            // d_out write is off the critical path (nothing polls it)
            if (lane < 8)
                out[(size_t)t * H + obase + o] = hn;
        } else {
            // ---------------- dot warps ----------------
            unsigned long long h2[4];
            if (t == 0) {
#pragma unroll
                for (int q = 0; q < 4; ++q) h2[q] = 0ULL;
            } else {
                const int slot = (t - 1) & 1;
                if (g == 0) {
                    // 2-deep pipelined poll+fetch on this CTA's replica
                    const float* base =
                        g_hline + (((size_t)myrep * 2 + slot) * NSM + p) * 32;
                    const unsigned want = (unsigned)t;  // tag of h_{t-1}
                    float Ra[12], Rb[12];
                    float hv0 = 0.f, hv1 = 0.f, hv2 = 0.f, hv3 = 0.f;
                    float hv4 = 0.f, hv5 = 0.f, hv6 = 0.f, hv7 = 0.f;
                    bool ok = false;
                    POLL_ISSUE(Ra);
                    for (;;) {
                        if (!ok) POLL_ISSUE(Rb);
                        POLL_TRY(Ra);
                        if (__all_sync(0xFFFFFFFFu, ok)) break;
                        if (!ok) POLL_ISSUE(Ra);
                        POLL_TRY(Rb);
                        if (__all_sync(0xFFFFFFFFu, ok)) break;
                    }
                    float4 lo = make_float4(hv0, hv1, hv2, hv3);
                    float4 hi = make_float4(hv4, hv5, hv6, hv7);
                    *(float4*)&s_h[c][lane * 8]     = lo;
                    *(float4*)&s_h[c][lane * 8 + 4] = hi;
                    h2[0] = pack2(lo.x, lo.y);
                    h2[1] = pack2(lo.z, lo.w);
                    h2[2] = pack2(hi.x, hi.y);
                    h2[3] = pack2(hi.z, hi.w);
                    // release siblings without blocking (leader has h in regs)
                    asm volatile("bar.arrive %0, %1;" :: "r"(c + 1), "r"(128)
                                 : "memory");
                } else {
                    asm volatile("bar.sync %0, %1;" :: "r"(c + 1), "r"(128)
                                 : "memory");
                    float4 a = *(const float4*)&s_h[c][lane * 8];
                    float4 b = *(const float4*)&s_h[c][lane * 8 + 4];
                    h2[0] = pack2(a.x, a.y);
                    h2[1] = pack2(a.z, a.w);
                    h2[2] = pack2(b.x, b.y);
                    h2[3] = pack2(b.z, b.w);
                }
            }

            float accv[6];
#pragma unroll
            for (int j = 0; j < 6; ++j) {
                unsigned long long acc = 0ULL;
#pragma unroll
                for (int q = 0; q < 4; ++q) acc = ffma2(w2[j][q], h2[q], acc);
                accv[j] = hsum2(acc);
            }
#pragma unroll
            for (int j = 0; j < 6; ++j) {
                accv[j] += __shfl_xor_sync(0xFFFFFFFFu, accv[j], 16);
                accv[j] += __shfl_xor_sync(0xFFFFFFFFu, accv[j], 8);
            }
            if (lane < 8) {
#pragma unroll
                for (int j = 0; j < 6; ++j)
                    partials[buf][g * 6 + j][c * 8 + lane] = accv[j];
            }
            // hand partials to the finalizer WITHOUT waiting for it, then
            // head straight into step t+1's poll (safe: partials are
            // double-buffered and t+2 reuse is tag-gated via remote CTAs)
            asm volatile("bar.arrive 7, %0;" :: "r"(SCAN_THREADS) : "memory");
        }
    }
#undef POLL_ISSUE
#undef POLL_TRY
}

// ---------------------------------------------------------------------------
extern "C" void kernel_launch(void* const* d_in, const int* in_sizes, int n_in,
                              void* d_out, int out_size)
{
    const float* inp  = (const float*)d_in[0];  // [8192, 1024]
    const float* W_ih = (const float*)d_in[1];  // [3072, 1024]
    const float* W_hh = (const float*)d_in[2];  // [3072, 1024]
    const float* b_ih = (const float*)d_in[3];  // [3072]
    const float* b_hh = (const float*)d_in[4];  // [3072]
    float* out = (float*)d_out;                 // [8192, 1024]

    // 1) reset exchange state (tags, gx-ready counters, tile counter)
    clear_kernel<<<32, 256>>>();

    // 2) fused: 128 scan CTAs + 24 work-stealing GEMM CTAs, one wave
    fused_kernel<<<NSM + NWORK, SCAN_THREADS>>>(inp, W_ih, b_ih,
                                                W_hh, b_hh, out);
}

// round 14
// speedup vs baseline: 1.2116x; 1.2116x over previous
#include <cuda_runtime.h>
#include <cstdint>

#define S 8192
#define H 1024
#define NSM 128
#define NWORK 24            // GEMM worker CTAs on spare SMs (GB300: 152 SMs)
#define SCAN_THREADS 544    // 16 dot-warps + finalizer warp 16 (highest wid)
#define NREP 4              // packet-line replicas (best measured, R10/R12)
#define NTILE_N 24          // 3072 / 128
#define NTILE_M 64          // 8192 / 128
#define NTILES (NTILE_M * NTILE_N)

// Scratch: input-side gate projections gx[S][3H].
__device__ float g_gx[(size_t)S * 3 * H];
// h-exchange lines, replicated x4 and double buffered:
//   [rep][slot][producer][32 floats] = one 128B line per (rep,slot,producer).
// Three self-validating 16B packets per line:
//   [tag h0 h1 h2] [tag h3 h4 h5] [tag h6 h7 pad]  (tag = step+1 as uint bits)
__device__ __align__(128) float g_hline[NREP * 2 * NSM * 32];
// per-m-block gx completion counters, padded to one 128B line each
__device__ __align__(128) unsigned int g_gxready[NTILE_M * 32];
// work-stealing tile counter for the GEMM workers
__device__ unsigned int g_tilectr;

// ---------------------------------------------------------------------------
// packed fp32x2 helpers (sm_103a FFMA2 path)
// ---------------------------------------------------------------------------
__device__ __forceinline__ unsigned long long pack2(float lo, float hi) {
    unsigned long long r;
    asm("mov.b64 %0, {%1, %2};" : "=l"(r) : "f"(lo), "f"(hi));
    return r;
}
__device__ __forceinline__ unsigned long long ffma2(unsigned long long a,
                                                    unsigned long long b,
                                                    unsigned long long c) {
    unsigned long long d;
    asm("fma.rn.f32x2 %0, %1, %2, %3;" : "=l"(d) : "l"(a), "l"(b), "l"(c));
    return d;
}
__device__ __forceinline__ float hsum2(unsigned long long a) {
    float lo, hi;
    asm("mov.b64 {%0, %1}, %2;" : "=f"(lo), "=f"(hi) : "l"(a));
    return lo + hi;
}

// ---------------------------------------------------------------------------
// Kernel 1: clear exchange state for this graph replay (runs first, tiny).
// ---------------------------------------------------------------------------
__global__ void clear_kernel() {
    int idx = blockIdx.x * blockDim.x + threadIdx.x;   // 32*256 = 8192
    float4 z = make_float4(0.f, 0.f, 0.f, 0.f);
    ((float4*)g_hline)[idx] = z;                       // 8192 float4 total
    if (idx < NTILE_M * 32) g_gxready[idx] = 0u;
    if (idx == 0) g_tilectr = 0u;
}

// ---------------------------------------------------------------------------
// Kernel 2 (fused): bids 0..127 = persistent GRU scan (R12 protocol + the
//                   barrier-decoupling change); bids 128..151 = GEMM workers.
//
// Decoupling (the only change vs R12): dot warps bar.ARRIVE(7) after their
// partials writes and head straight into step t+1's poll; only the finalizer
// bar.SYNCs(7). Chunk leaders bar.ARRIVE(c+1) after the smem relay (their h
// is already in registers); siblings bar.sync(c+1).
// Safety: the leader's step-t+1 poll passes only after ALL producers publish
// tag t+1, including this CTA, whose finalizer's bar.sync(7) at step t
// required every sibling's step-t arrival -- which happens after their s_h
// reads and partials writes. So s_h (single-buffer) and partials (double-
// buffer) reuse are both ordered.
// ---------------------------------------------------------------------------
__global__ __launch_bounds__(SCAN_THREADS, 1) void fused_kernel(
    const float* __restrict__ A,      // inp [S,1024]
    const float* __restrict__ Wih,    // [3072,1024]
    const float* __restrict__ bih,    // [3072]
    const float* __restrict__ Whh,    // [3072,1024]
    const float* __restrict__ bhh,    // [3072]
    float* __restrict__ out)          // [S,1024]
{
    const int tid  = threadIdx.x;
    const int warp = tid >> 5;
    const int lane = tid & 31;
    const int bid  = blockIdx.x;

    if (bid >= NSM) {
        // ================= GEMM worker: gx = inp @ Wih^T + bih =============
        __shared__ __align__(16) float As[16][132];
        __shared__ __align__(16) float Bs[16][132];
        __shared__ int s_tile;
        const bool act = (tid < 256);
        const int tx = tid & 15;
        const int ty = (tid >> 4) & 15;

        for (;;) {
            if (tid == 0) s_tile = (int)atomicAdd(&g_tilectr, 1u);
            __syncthreads();
            const int ti = s_tile;
            if (ti >= NTILES) break;
            const int mb = ti / NTILE_N;
            const int m0 = mb * 128;
            const int n0 = (ti - mb * NTILE_N) * 128;

            unsigned long long acc2[8][4];
#pragma unroll
            for (int i = 0; i < 8; ++i)
#pragma unroll
                for (int q = 0; q < 4; ++q) acc2[i][q] = 0ULL;

            for (int kt = 0; kt < 1024; kt += 16) {
                if (act) {
#pragma unroll
                    for (int r = 0; r < 2; ++r) {
                        int idx = tid + r * 256;
                        int row = idx >> 2;
                        int kq  = idx & 3;
                        float4 v = *(const float4*)(A + (size_t)(m0 + row) * 1024 + kt + kq * 4);
                        As[kq * 4 + 0][row] = v.x;
                        As[kq * 4 + 1][row] = v.y;
                        As[kq * 4 + 2][row] = v.z;
                        As[kq * 4 + 3][row] = v.w;
                    }
#pragma unroll
                    for (int r = 0; r < 2; ++r) {
                        int idx = tid + r * 256;
                        int n  = idx >> 2;
                        int kq = idx & 3;
                        float4 v = *(const float4*)(Wih + (size_t)(n0 + n) * 1024 + kt + kq * 4);
                        Bs[kq * 4 + 0][n] = v.x;
                        Bs[kq * 4 + 1][n] = v.y;
                        Bs[kq * 4 + 2][n] = v.z;
                        Bs[kq * 4 + 3][n] = v.w;
                    }
                }
                __syncthreads();
                if (act) {
#pragma unroll
                    for (int k = 0; k < 16; ++k) {
                        float4 b0 = *(const float4*)&Bs[k][tx * 8];
                        float4 b1 = *(const float4*)&Bs[k][tx * 8 + 4];
                        unsigned long long rb2[4];
                        rb2[0] = pack2(b0.x, b0.y);
                        rb2[1] = pack2(b0.z, b0.w);
                        rb2[2] = pack2(b1.x, b1.y);
                        rb2[3] = pack2(b1.z, b1.w);
#pragma unroll
                        for (int i = 0; i < 8; ++i) {
                            float a = As[k][ty * 8 + i];
                            unsigned long long a2 = pack2(a, a);
#pragma unroll
                            for (int q = 0; q < 4; ++q)
                                acc2[i][q] = ffma2(a2, rb2[q], acc2[i][q]);
                        }
                    }
                }
                __syncthreads();
            }

            if (act) {
#pragma unroll
                for (int i = 0; i < 8; ++i) {
                    size_t rowoff = (size_t)(m0 + ty * 8 + i) * 3072 + n0 + tx * 8;
#pragma unroll
                    for (int jq = 0; jq < 2; ++jq) {
                        float lo0, hi0, lo1, hi1;
                        asm("mov.b64 {%0, %1}, %2;" : "=f"(lo0), "=f"(hi0) : "l"(acc2[i][jq * 2 + 0]));
                        asm("mov.b64 {%0, %1}, %2;" : "=f"(lo1), "=f"(hi1) : "l"(acc2[i][jq * 2 + 1]));
                        float4 v;
                        v.x = lo0 + bih[n0 + tx * 8 + jq * 4 + 0];
                        v.y = hi0 + bih[n0 + tx * 8 + jq * 4 + 1];
                        v.z = lo1 + bih[n0 + tx * 8 + jq * 4 + 2];
                        v.w = hi1 + bih[n0 + tx * 8 + jq * 4 + 3];
                        *(float4*)(g_gx + rowoff + jq * 4) = v;
                    }
                }
            }
            __threadfence();     // make this thread's gx stores GPU-visible
            __syncthreads();     // all threads' fences done before the flag
            if (tid == 0) {
                asm volatile("red.release.gpu.global.add.u32 [%0], 1;"
                             :: "l"(&g_gxready[mb * 32]) : "memory");
            }
        }
        return;
    }

    // ==================== persistent GRU scan ==============================
    const int obase = bid * 8;

    __shared__ __align__(16) float s_h[4][256];        // per-chunk h relay
    __shared__ __align__(16) float partials[2][24][36];

    const bool isfin = (warp == 16);
    const int c = warp & 3;              // k-chunk (0..3): leaders on SMSP 0..3
    const int g = warp >> 2;             // row-group (0..3)
    const int k0 = c * 256 + lane * 8;
    const int p  = c * 32 + lane;        // producer this lane covers (g==0)
    const int myrep = bid & (NREP - 1);  // replica this CTA polls

    // ---- dot-warp setup: 6 gate-rows x 8 cols of W_hh, packed f32x2 ----
    unsigned long long w2[6][4];
    if (!isfin) {
#pragma unroll
        for (int j = 0; j < 6; ++j) {
            int gr  = g * 6 + j;                          // 0..23
            int row = (gr >> 3) * H + obase + (gr & 7);   // gate*H + out idx
            const float4* pw = (const float4*)(Whh + (size_t)row * H + k0);
            float4 a = pw[0], b = pw[1];
            w2[j][0] = pack2(a.x, a.y);
            w2[j][1] = pack2(a.z, a.w);
            w2[j][2] = pack2(b.x, b.y);
            w2[j][3] = pack2(b.z, b.w);
        }
    }

    // ---- finalizer setup ----
    const int o = lane & 7;
    float bh = 0.f;
    if (isfin && lane < 24) bh = bhh[(lane >> 3) * H + obase + o];
    float hprev = 0.f;                   // lanes 0..7 carry h for their dim
    const size_t gx_lane_off = (size_t)(lane >> 3) * H + obase + o;

    for (int t = 0; t < S; ++t) {
        const int buf = t & 1;

        if (isfin) {
            // gate on gx availability once per m-block (128 steps)
            if ((t & 127) == 0) {
                const unsigned int* rp = &g_gxready[(t >> 7) * 32];
                unsigned int v;
                do {
                    asm volatile("ld.acquire.gpu.global.u32 %0, [%1];"
                                 : "=r"(v) : "l"(rp) : "memory");
                } while (v < (unsigned)NTILE_N);
            }
            // prefetch gx (L2, bypass L1 -- written by worker SMs)
            float gxv = 0.f;
            if (lane < 24)
                gxv = __ldcg(&g_gx[(size_t)t * (3 * H) + gx_lane_off]);

            // wait for all 16 dot warps' partials (they only bar.arrive)
            asm volatile("bar.sync 7, %0;" :: "r"(SCAN_THREADS) : "memory");

            float s = 0.f;
            if (lane < 24) {
                const float4* pr = (const float4*)(&partials[buf][lane][0]);
                float4 p0 = pr[0], p1 = pr[1], p2 = pr[2], p3 = pr[3];
                float4 p4 = pr[4], p5 = pr[5], p6 = pr[6], p7 = pr[7];
                float4 q0, q1, q2, q3, r0, r1, f;
                q0.x = p0.x + p1.x; q0.y = p0.y + p1.y; q0.z = p0.z + p1.z; q0.w = p0.w + p1.w;
                q1.x = p2.x + p3.x; q1.y = p2.y + p3.y; q1.z = p2.z + p3.z; q1.w = p2.w + p3.w;
                q2.x = p4.x + p5.x; q2.y = p4.y + p5.y; q2.z = p4.z + p5.z; q2.w = p4.w + p5.w;
                q3.x = p6.x + p7.x; q3.y = p6.y + p7.y; q3.z = p6.z + p7.z; q3.w = p6.w + p7.w;
                r0.x = q0.x + q1.x; r0.y = q0.y + q1.y; r0.z = q0.z + q1.z; r0.w = q0.w + q1.w;
                r1.x = q2.x + q3.x; r1.y = q2.y + q3.y; r1.z = q2.z + q3.z; r1.w = q2.w + q3.w;
                f.x = r0.x + r1.x; f.y = r0.y + r1.y; f.z = r0.z + r1.z; f.w = r0.w + r1.w;
                s = bh + ((f.x + f.y) + (f.z + f.w));
            }
            // lanes 0..15: r/z pre-activations include gx; lanes 16..23 keep
            // the hidden n-side separate (r gates only the hidden part)
            float val = s + ((lane < 16) ? gxv : 0.f);
            float sig = __fdividef(1.f, 1.f + __expf(-val));  // 24 parallel
            float v_n  = __shfl_sync(0xFFFFFFFFu, s,   o + 16);
            float gx_n = __shfl_sync(0xFFFFFFFFu, gxv, o + 16);
            float zz   = __shfl_sync(0xFFFFFFFFu, sig, o + 8);
            float hn = 0.f;
            if (lane < 8) {
                float r  = sig;
                float a  = gx_n + r * v_n;
                float e2 = __expf(2.f * a);
                float n  = 1.f - __fdividef(2.f, e2 + 1.f);   // tanh(a)
                hn = zz * (hprev - n) + n;                    // (1-z)*n + z*h
                hprev = hn;
            }
            // ---- publish: 12 packets (3 per replica x 4), no fence ----
            {
                const unsigned tagv = (unsigned)(t + 1);
                const int j   = lane - (lane / 3) * 3;   // lane % 3
                const int rep = lane / 3;                // 0..3 for lane<12
                int s0 = (3 * j)     & 31;
                int s1 = (3 * j + 1) & 31;
                int s2 = (3 * j + 2) & 31;
                float x = __shfl_sync(0xFFFFFFFFu, hn, s0);
                float y = __shfl_sync(0xFFFFFFFFu, hn, s1);
                float z = __shfl_sync(0xFFFFFFFFu, hn, s2);
                if (lane < 12) {
                    float* dst = &g_hline[(((size_t)rep * 2 + buf) * NSM + bid)
                                          * 32 + j * 4];
                    asm volatile(
                        "st.volatile.global.v4.f32 [%0], {%1, %2, %3, %4};"
                        :: "l"(dst), "f"(__uint_as_float(tagv)),
                           "f"(x), "f"(y), "f"(z) : "memory");
                }
            }
            // d_out write is off the critical path (nothing polls it)
            if (lane < 8)
                out[(size_t)t * H + obase + o] = hn;
        } else {
            // ---------------- dot warps ----------------
            unsigned long long h2[4];
            if (t == 0) {
#pragma unroll
                for (int q = 0; q < 4; ++q) h2[q] = 0ULL;
            } else {
                const int slot = (t - 1) & 1;
                if (g == 0) {
                    // fused poll+fetch on THIS CTA's replica of producer p's
                    // line; per-lane predicated (stop loading once seen)
                    const float* base =
                        g_hline + (((size_t)myrep * 2 + slot) * NSM + p) * 32;
                    const unsigned want = (unsigned)t;  // tag of h_{t-1}
                    float a0 = 0.f, a1 = 0.f, a2 = 0.f, a3 = 0.f;
                    float b0 = 0.f, b1 = 0.f, b2 = 0.f, b3 = 0.f;
                    float c0 = 0.f, c1 = 0.f, c2 = 0.f, c3 = 0.f;
                    bool ok = false;
                    do {
                        if (!ok) {
                            asm volatile(
                                "ld.volatile.global.v4.f32 {%0,%1,%2,%3}, [%4];"
                                : "=f"(a0), "=f"(a1), "=f"(a2), "=f"(a3)
                                : "l"(base));
                            asm volatile(
                                "ld.volatile.global.v4.f32 {%0,%1,%2,%3}, [%4];"
                                : "=f"(b0), "=f"(b1), "=f"(b2), "=f"(b3)
                                : "l"(base + 4));
                            asm volatile(
                                "ld.volatile.global.v4.f32 {%0,%1,%2,%3}, [%4];"
                                : "=f"(c0), "=f"(c1), "=f"(c2), "=f"(c3)
                                : "l"(base + 8));
                            ok = (__float_as_uint(a0) == want) &
                                 (__float_as_uint(b0) == want) &
                                 (__float_as_uint(c0) == want);
                        }
                    } while (!__all_sync(0xFFFFFFFFu, ok));
                    // h = {a1,a2,a3, b1,b2,b3, c1,c2}
                    float4 lo = make_float4(a1, a2, a3, b1);
                    float4 hi = make_float4(b2, b3, c1, c2);
                    *(float4*)&s_h[c][lane * 8]     = lo;
                    *(float4*)&s_h[c][lane * 8 + 4] = hi;
                    h2[0] = pack2(lo.x, lo.y);
                    h2[1] = pack2(lo.z, lo.w);
                    h2[2] = pack2(hi.x, hi.y);
                    h2[3] = pack2(hi.z, hi.w);
                    // release siblings without blocking (leader has h in regs)
                    asm volatile("bar.arrive %0, %1;" :: "r"(c + 1), "r"(128)
                                 : "memory");
                } else {
                    asm volatile("bar.sync %0, %1;" :: "r"(c + 1), "r"(128)
                                 : "memory");
                    float4 a = *(const float4*)&s_h[c][lane * 8];
                    float4 b = *(const float4*)&s_h[c][lane * 8 + 4];
                    h2[0] = pack2(a.x, a.y);
                    h2[1] = pack2(a.z, a.w);
                    h2[2] = pack2(b.x, b.y);
                    h2[3] = pack2(b.z, b.w);
                }
            }

            float accv[6];
#pragma unroll
            for (int j = 0; j < 6; ++j) {
                unsigned long long acc = 0ULL;
#pragma unroll
                for (int q = 0; q < 4; ++q) acc = ffma2(w2[j][q], h2[q], acc);
                accv[j] = hsum2(acc);
            }
#pragma unroll
            for (int j = 0; j < 6; ++j) {
                accv[j] += __shfl_xor_sync(0xFFFFFFFFu, accv[j], 16);
                accv[j] += __shfl_xor_sync(0xFFFFFFFFu, accv[j], 8);
            }
            if (lane < 8) {
#pragma unroll
                for (int j = 0; j < 6; ++j)
                    partials[buf][g * 6 + j][c * 8 + lane] = accv[j];
            }
            // hand partials to the finalizer WITHOUT waiting for it, then
            // head straight into step t+1's poll (safe: partials are
            // double-buffered; s_h reuse is ordered through this CTA's own
            // publish, which the next poll requires)
            asm volatile("bar.arrive 7, %0;" :: "r"(SCAN_THREADS) : "memory");
        }
    }
}

// ---------------------------------------------------------------------------
extern "C" void kernel_launch(void* const* d_in, const int* in_sizes, int n_in,
                              void* d_out, int out_size)
{
    const float* inp  = (const float*)d_in[0];  // [8192, 1024]
    const float* W_ih = (const float*)d_in[1];  // [3072, 1024]
    const float* W_hh = (const float*)d_in[2];  // [3072, 1024]
    const float* b_ih = (const float*)d_in[3];  // [3072]
    const float* b_hh = (const float*)d_in[4];  // [3072]
    float* out = (float*)d_out;                 // [8192, 1024]

    // 1) reset exchange state (tags, gx-ready counters, tile counter)
    clear_kernel<<<32, 256>>>();

    // 2) fused: 128 scan CTAs + 24 work-stealing GEMM CTAs, one wave
    fused_kernel<<<NSM + NWORK, SCAN_THREADS>>>(inp, W_ih, b_ih,
                                                W_hh, b_hh, out);
}

// round 15
// speedup vs baseline: 1.2169x; 1.0044x over previous
#include <cuda_runtime.h>
#include <cstdint>

#define S 8192
#define H 1024
#define NSM 128
#define NWORK 24            // GEMM worker CTAs on spare SMs (GB300: 152 SMs)
#define SCAN_THREADS 544    // 16 dot-warps + finalizer warp 16 (highest wid)
#define NREP 4              // packet-line replicas (best measured, R10/R12)
#define NTILE_N 24          // 3072 / 128
#define NTILE_M 64          // 8192 / 128
#define NTILES (NTILE_M * NTILE_N)

// Scratch: input-side gate projections gx[S][3H].
__device__ float g_gx[(size_t)S * 3 * H];
// h-exchange lines, replicated x4 and double buffered:
//   [rep][slot][producer][32 floats] = one 128B line per (rep,slot,producer).
// Three self-validating 16B packets per line:
//   [tag h0 h1 h2] [tag h3 h4 h5] [tag h6 h7 pad]  (tag = step+1 as uint bits)
__device__ __align__(128) float g_hline[NREP * 2 * NSM * 32];
// per-m-block gx completion counters, padded to one 128B line each
__device__ __align__(128) unsigned int g_gxready[NTILE_M * 32];
// work-stealing tile counter for the GEMM workers
__device__ unsigned int g_tilectr;
// scan-finished flag: workers burn (clock hold) until this flips
__device__ __align__(128) unsigned int g_done[32];

// ---------------------------------------------------------------------------
// packed fp32x2 helpers (sm_103a FFMA2 path)
// ---------------------------------------------------------------------------
__device__ __forceinline__ unsigned long long pack2(float lo, float hi) {
    unsigned long long r;
    asm("mov.b64 %0, {%1, %2};" : "=l"(r) : "f"(lo), "f"(hi));
    return r;
}
__device__ __forceinline__ unsigned long long ffma2(unsigned long long a,
                                                    unsigned long long b,
                                                    unsigned long long c) {
    unsigned long long d;
    asm("fma.rn.f32x2 %0, %1, %2, %3;" : "=l"(d) : "l"(a), "l"(b), "l"(c));
    return d;
}
__device__ __forceinline__ float hsum2(unsigned long long a) {
    float lo, hi;
    asm("mov.b64 {%0, %1}, %2;" : "=f"(lo), "=f"(hi) : "l"(a));
    return lo + hi;
}

// ---------------------------------------------------------------------------
// Kernel 1: clear exchange state for this graph replay (runs first, tiny).
// ---------------------------------------------------------------------------
__global__ void clear_kernel() {
    int idx = blockIdx.x * blockDim.x + threadIdx.x;   // 32*256 = 8192
    float4 z = make_float4(0.f, 0.f, 0.f, 0.f);
    ((float4*)g_hline)[idx] = z;                       // 8192 float4 total
    if (idx < NTILE_M * 32) g_gxready[idx] = 0u;
    if (idx == 0) g_tilectr = 0u;
    if (idx < 32) g_done[idx] = 0u;
}

// ---------------------------------------------------------------------------
// Kernel 2 (fused): bids 0..127 = persistent GRU scan (R14 protocol);
//                   bids 128..151 = GEMM workers, then clock-hold burn.
// ---------------------------------------------------------------------------
__global__ __launch_bounds__(SCAN_THREADS, 1) void fused_kernel(
    const float* __restrict__ A,      // inp [S,1024]
    const float* __restrict__ Wih,    // [3072,1024]
    const float* __restrict__ bih,    // [3072]
    const float* __restrict__ Whh,    // [3072,1024]
    const float* __restrict__ bhh,    // [3072]
    float* __restrict__ out)          // [S,1024]
{
    const int tid  = threadIdx.x;
    const int warp = tid >> 5;
    const int lane = tid & 31;
    const int bid  = blockIdx.x;

    if (bid >= NSM) {
        // ================= GEMM worker: gx = inp @ Wih^T + bih =============
        __shared__ __align__(16) float As[16][132];
        __shared__ __align__(16) float Bs[16][132];
        __shared__ int s_tile;
        const bool act = (tid < 256);
        const int tx = tid & 15;
        const int ty = (tid >> 4) & 15;

        for (;;) {
            if (tid == 0) s_tile = (int)atomicAdd(&g_tilectr, 1u);
            __syncthreads();
            const int ti = s_tile;
            if (ti >= NTILES) break;
            const int mb = ti / NTILE_N;
            const int m0 = mb * 128;
            const int n0 = (ti - mb * NTILE_N) * 128;

            unsigned long long acc2[8][4];
#pragma unroll
            for (int i = 0; i < 8; ++i)
#pragma unroll
                for (int q = 0; q < 4; ++q) acc2[i][q] = 0ULL;

            for (int kt = 0; kt < 1024; kt += 16) {
                if (act) {
#pragma unroll
                    for (int r = 0; r < 2; ++r) {
                        int idx = tid + r * 256;
                        int row = idx >> 2;
                        int kq  = idx & 3;
                        float4 v = *(const float4*)(A + (size_t)(m0 + row) * 1024 + kt + kq * 4);
                        As[kq * 4 + 0][row] = v.x;
                        As[kq * 4 + 1][row] = v.y;
                        As[kq * 4 + 2][row] = v.z;
                        As[kq * 4 + 3][row] = v.w;
                    }
#pragma unroll
                    for (int r = 0; r < 2; ++r) {
                        int idx = tid + r * 256;
                        int n  = idx >> 2;
                        int kq = idx & 3;
                        float4 v = *(const float4*)(Wih + (size_t)(n0 + n) * 1024 + kt + kq * 4);
                        Bs[kq * 4 + 0][n] = v.x;
                        Bs[kq * 4 + 1][n] = v.y;
                        Bs[kq * 4 + 2][n] = v.z;
                        Bs[kq * 4 + 3][n] = v.w;
                    }
                }
                __syncthreads();
                if (act) {
#pragma unroll
                    for (int k = 0; k < 16; ++k) {
                        float4 b0 = *(const float4*)&Bs[k][tx * 8];
                        float4 b1 = *(const float4*)&Bs[k][tx * 8 + 4];
                        unsigned long long rb2[4];
                        rb2[0] = pack2(b0.x, b0.y);
                        rb2[1] = pack2(b0.z, b0.w);
                        rb2[2] = pack2(b1.x, b1.y);
                        rb2[3] = pack2(b1.z, b1.w);
#pragma unroll
                        for (int i = 0; i < 8; ++i) {
                            float a = As[k][ty * 8 + i];
                            unsigned long long a2 = pack2(a, a);
#pragma unroll
                            for (int q = 0; q < 4; ++q)
                                acc2[i][q] = ffma2(a2, rb2[q], acc2[i][q]);
                        }
                    }
                }
                __syncthreads();
            }

            if (act) {
#pragma unroll
                for (int i = 0; i < 8; ++i) {
                    size_t rowoff = (size_t)(m0 + ty * 8 + i) * 3072 + n0 + tx * 8;
#pragma unroll
                    for (int jq = 0; jq < 2; ++jq) {
                        float lo0, hi0, lo1, hi1;
                        asm("mov.b64 {%0, %1}, %2;" : "=f"(lo0), "=f"(hi0) : "l"(acc2[i][jq * 2 + 0]));
                        asm("mov.b64 {%0, %1}, %2;" : "=f"(lo1), "=f"(hi1) : "l"(acc2[i][jq * 2 + 1]));
                        float4 v;
                        v.x = lo0 + bih[n0 + tx * 8 + jq * 4 + 0];
                        v.y = hi0 + bih[n0 + tx * 8 + jq * 4 + 1];
                        v.z = lo1 + bih[n0 + tx * 8 + jq * 4 + 2];
                        v.w = hi1 + bih[n0 + tx * 8 + jq * 4 + 3];
                        *(float4*)(g_gx + rowoff + jq * 4) = v;
                    }
                }
            }
            __threadfence();     // make this thread's gx stores GPU-visible
            __syncthreads();     // all threads' fences done before the flag
            if (tid == 0) {
                asm volatile("red.release.gpu.global.add.u32 [%0], 1;"
                             :: "l"(&g_gxready[mb * 32]) : "memory");
            }
        }

        // ---- clock-hold burn: keep these 24 SMs at high IPC until the ----
        // ---- scan finishes, so the chip-global GPCCLK stays boosted.  ----
        {
            float r0 = 1.0f + lane * 1e-6f, r1 = 1.1f, r2 = 1.2f, r3 = 1.3f;
            float r4 = 1.4f, r5 = 1.5f, r6 = 1.6f, r7 = 1.7f;
            const float m = 0.9999999f, a = 1e-7f;
            for (;;) {
                unsigned int d;
                asm volatile("ld.relaxed.gpu.global.u32 %0, [%1];"
                             : "=r"(d) : "l"(&g_done[0]) : "memory");
                if (d) break;
#pragma unroll
                for (int it = 0; it < 256; ++it) {
                    asm volatile("fma.rn.f32 %0, %0, %1, %2;" : "+f"(r0) : "f"(m), "f"(a));
                    asm volatile("fma.rn.f32 %0, %0, %1, %2;" : "+f"(r1) : "f"(m), "f"(a));
                    asm volatile("fma.rn.f32 %0, %0, %1, %2;" : "+f"(r2) : "f"(m), "f"(a));
                    asm volatile("fma.rn.f32 %0, %0, %1, %2;" : "+f"(r3) : "f"(m), "f"(a));
                    asm volatile("fma.rn.f32 %0, %0, %1, %2;" : "+f"(r4) : "f"(m), "f"(a));
                    asm volatile("fma.rn.f32 %0, %0, %1, %2;" : "+f"(r5) : "f"(m), "f"(a));
                    asm volatile("fma.rn.f32 %0, %0, %1, %2;" : "+f"(r6) : "f"(m), "f"(a));
                    asm volatile("fma.rn.f32 %0, %0, %1, %2;" : "+f"(r7) : "f"(m), "f"(a));
                }
            }
        }
        return;
    }

    // ==================== persistent GRU scan (R14, unchanged) =============
    const int obase = bid * 8;

    __shared__ __align__(16) float s_h[4][256];        // per-chunk h relay
    __shared__ __align__(16) float partials[2][24][36];

    const bool isfin = (warp == 16);
    const int c = warp & 3;              // k-chunk (0..3): leaders on SMSP 0..3
    const int g = warp >> 2;             // row-group (0..3)
    const int k0 = c * 256 + lane * 8;
    const int p  = c * 32 + lane;        // producer this lane covers (g==0)
    const int myrep = bid & (NREP - 1);  // replica this CTA polls

    // ---- dot-warp setup: 6 gate-rows x 8 cols of W_hh, packed f32x2 ----
    unsigned long long w2[6][4];
    if (!isfin) {
#pragma unroll
        for (int j = 0; j < 6; ++j) {
            int gr  = g * 6 + j;                          // 0..23
            int row = (gr >> 3) * H + obase + (gr & 7);   // gate*H + out idx
            const float4* pw = (const float4*)(Whh + (size_t)row * H + k0);
            float4 a = pw[0], b = pw[1];
            w2[j][0] = pack2(a.x, a.y);
            w2[j][1] = pack2(a.z, a.w);
            w2[j][2] = pack2(b.x, b.y);
            w2[j][3] = pack2(b.z, b.w);
        }
    }

    // ---- finalizer setup ----
    const int o = lane & 7;
    float bh = 0.f;
    if (isfin && lane < 24) bh = bhh[(lane >> 3) * H + obase + o];
    float hprev = 0.f;                   // lanes 0..7 carry h for their dim
    const size_t gx_lane_off = (size_t)(lane >> 3) * H + obase + o;

    for (int t = 0; t < S; ++t) {
        const int buf = t & 1;

        if (isfin) {
            // gate on gx availability once per m-block (128 steps)
            if ((t & 127) == 0) {
                const unsigned int* rp = &g_gxready[(t >> 7) * 32];
                unsigned int v;
                do {
                    asm volatile("ld.acquire.gpu.global.u32 %0, [%1];"
                                 : "=r"(v) : "l"(rp) : "memory");
                } while (v < (unsigned)NTILE_N);
            }
            // prefetch gx (L2, bypass L1 -- written by worker SMs)
            float gxv = 0.f;
            if (lane < 24)
                gxv = __ldcg(&g_gx[(size_t)t * (3 * H) + gx_lane_off]);

            // wait for all 16 dot warps' partials (they only bar.arrive)
            asm volatile("bar.sync 7, %0;" :: "r"(SCAN_THREADS) : "memory");

            float s = 0.f;
            if (lane < 24) {
                const float4* pr = (const float4*)(&partials[buf][lane][0]);
                float4 p0 = pr[0], p1 = pr[1], p2 = pr[2], p3 = pr[3];
                float4 p4 = pr[4], p5 = pr[5], p6 = pr[6], p7 = pr[7];
                float4 q0, q1, q2, q3, r0, r1, f;
                q0.x = p0.x + p1.x; q0.y = p0.y + p1.y; q0.z = p0.z + p1.z; q0.w = p0.w + p1.w;
                q1.x = p2.x + p3.x; q1.y = p2.y + p3.y; q1.z = p2.z + p3.z; q1.w = p2.w + p3.w;
                q2.x = p4.x + p5.x; q2.y = p4.y + p5.y; q2.z = p4.z + p5.z; q2.w = p4.w + p5.w;
                q3.x = p6.x + p7.x; q3.y = p6.y + p7.y; q3.z = p6.z + p7.z; q3.w = p6.w + p7.w;
                r0.x = q0.x + q1.x; r0.y = q0.y + q1.y; r0.z = q0.z + q1.z; r0.w = q0.w + q1.w;
                r1.x = q2.x + q3.x; r1.y = q2.y + q3.y; r1.z = q2.z + q3.z; r1.w = q2.w + q3.w;
                f.x = r0.x + r1.x; f.y = r0.y + r1.y; f.z = r0.z + r1.z; f.w = r0.w + r1.w;
                s = bh + ((f.x + f.y) + (f.z + f.w));
            }
            // lanes 0..15: r/z pre-activations include gx; lanes 16..23 keep
            // the hidden n-side separate (r gates only the hidden part)
            float val = s + ((lane < 16) ? gxv : 0.f);
            float sig = __fdividef(1.f, 1.f + __expf(-val));  // 24 parallel
            float v_n  = __shfl_sync(0xFFFFFFFFu, s,   o + 16);
            float gx_n = __shfl_sync(0xFFFFFFFFu, gxv, o + 16);
            float zz   = __shfl_sync(0xFFFFFFFFu, sig, o + 8);
            float hn = 0.f;
            if (lane < 8) {
                float r  = sig;
                float a  = gx_n + r * v_n;
                float e2 = __expf(2.f * a);
                float n  = 1.f - __fdividef(2.f, e2 + 1.f);   // tanh(a)
                hn = zz * (hprev - n) + n;                    // (1-z)*n + z*h
                hprev = hn;
            }
            // ---- publish: 12 packets (3 per replica x 4), no fence ----
            {
                const unsigned tagv = (unsigned)(t + 1);
                const int j   = lane - (lane / 3) * 3;   // lane % 3
                const int rep = lane / 3;                // 0..3 for lane<12
                int s0 = (3 * j)     & 31;
                int s1 = (3 * j + 1) & 31;
                int s2 = (3 * j + 2) & 31;
                float x = __shfl_sync(0xFFFFFFFFu, hn, s0);
                float y = __shfl_sync(0xFFFFFFFFu, hn, s1);
                float z = __shfl_sync(0xFFFFFFFFu, hn, s2);
                if (lane < 12) {
                    float* dst = &g_hline[(((size_t)rep * 2 + buf) * NSM + bid)
                                          * 32 + j * 4];
                    asm volatile(
                        "st.volatile.global.v4.f32 [%0], {%1, %2, %3, %4};"
                        :: "l"(dst), "f"(__uint_as_float(tagv)),
                           "f"(x), "f"(y), "f"(z) : "memory");
                }
            }
            // d_out write is off the critical path (nothing polls it)
            if (lane < 8)
                out[(size_t)t * H + obase + o] = hn;
        } else {
            // ---------------- dot warps ----------------
            unsigned long long h2[4];
            if (t == 0) {
#pragma unroll
                for (int q = 0; q < 4; ++q) h2[q] = 0ULL;
            } else {
                const int slot = (t - 1) & 1;
                if (g == 0) {
                    // fused poll+fetch on THIS CTA's replica of producer p's
                    // line; per-lane predicated (stop loading once seen)
                    const float* base =
                        g_hline + (((size_t)myrep * 2 + slot) * NSM + p) * 32;
                    const unsigned want = (unsigned)t;  // tag of h_{t-1}
                    float a0 = 0.f, a1 = 0.f, a2 = 0.f, a3 = 0.f;
                    float b0 = 0.f, b1 = 0.f, b2 = 0.f, b3 = 0.f;
                    float c0 = 0.f, c1 = 0.f, c2 = 0.f, c3 = 0.f;
                    bool ok = false;
                    do {
                        if (!ok) {
                            asm volatile(
                                "ld.volatile.global.v4.f32 {%0,%1,%2,%3}, [%4];"
                                : "=f"(a0), "=f"(a1), "=f"(a2), "=f"(a3)
                                : "l"(base));
                            asm volatile(
                                "ld.volatile.global.v4.f32 {%0,%1,%2,%3}, [%4];"
                                : "=f"(b0), "=f"(b1), "=f"(b2), "=f"(b3)
                                : "l"(base + 4));
                            asm volatile(
                                "ld.volatile.global.v4.f32 {%0,%1,%2,%3}, [%4];"
                                : "=f"(c0), "=f"(c1), "=f"(c2), "=f"(c3)
                                : "l"(base + 8));
                            ok = (__float_as_uint(a0) == want) &
                                 (__float_as_uint(b0) == want) &
                                 (__float_as_uint(c0) == want);
                        }
                    } while (!__all_sync(0xFFFFFFFFu, ok));
                    // h = {a1,a2,a3, b1,b2,b3, c1,c2}
                    float4 lo = make_float4(a1, a2, a3, b1);
                    float4 hi = make_float4(b2, b3, c1, c2);
                    *(float4*)&s_h[c][lane * 8]     = lo;
                    *(float4*)&s_h[c][lane * 8 + 4] = hi;
                    h2[0] = pack2(lo.x, lo.y);
                    h2[1] = pack2(lo.z, lo.w);
                    h2[2] = pack2(hi.x, hi.y);
                    h2[3] = pack2(hi.z, hi.w);
                    // release siblings without blocking (leader has h in regs)
                    asm volatile("bar.arrive %0, %1;" :: "r"(c + 1), "r"(128)
                                 : "memory");
                } else {
                    asm volatile("bar.sync %0, %1;" :: "r"(c + 1), "r"(128)
                                 : "memory");
                    float4 a = *(const float4*)&s_h[c][lane * 8];
                    float4 b = *(const float4*)&s_h[c][lane * 8 + 4];
                    h2[0] = pack2(a.x, a.y);
                    h2[1] = pack2(a.z, a.w);
                    h2[2] = pack2(b.x, b.y);
                    h2[3] = pack2(b.z, b.w);
                }
            }

            float accv[6];
#pragma unroll
            for (int j = 0; j < 6; ++j) {
                unsigned long long acc = 0ULL;
#pragma unroll
                for (int q = 0; q < 4; ++q) acc = ffma2(w2[j][q], h2[q], acc);
                accv[j] = hsum2(acc);
            }
#pragma unroll
            for (int j = 0; j < 6; ++j) {
                accv[j] += __shfl_xor_sync(0xFFFFFFFFu, accv[j], 16);
                accv[j] += __shfl_xor_sync(0xFFFFFFFFu, accv[j], 8);
            }
            if (lane < 8) {
#pragma unroll
                for (int j = 0; j < 6; ++j)
                    partials[buf][g * 6 + j][c * 8 + lane] = accv[j];
            }
            // hand partials to the finalizer WITHOUT waiting for it, then
            // head straight into step t+1's poll (safe: partials are
            // double-buffered; s_h reuse is ordered through this CTA's own
            // publish, which the next poll requires)
            asm volatile("bar.arrive 7, %0;" :: "r"(SCAN_THREADS) : "memory");
        }
    }

    // scan finished: CTA 0 releases the burn loop on the worker SMs
    if (bid == 0 && isfin && lane == 0) {
        asm volatile("st.relaxed.gpu.global.u32 [%0], 1;"
                     :: "l"(&g_done[0]) : "memory");
    }
}

// ---------------------------------------------------------------------------
extern "C" void kernel_launch(void* const* d_in, const int* in_sizes, int n_in,
                              void* d_out, int out_size)
{
    const float* inp  = (const float*)d_in[0];  // [8192, 1024]
    const float* W_ih = (const float*)d_in[1];  // [3072, 1024]
    const float* W_hh = (const float*)d_in[2];  // [3072, 1024]
    const float* b_ih = (const float*)d_in[3];  // [3072]
    const float* b_hh = (const float*)d_in[4];  // [3072]
    float* out = (float*)d_out;                 // [8192, 1024]

    // 1) reset exchange state (tags, gx-ready counters, tile counter, done)
    clear_kernel<<<32, 256>>>();

    // 2) fused: 128 scan CTAs + 24 GEMM/burn CTAs, one wave
    fused_kernel<<<NSM + NWORK, SCAN_THREADS>>>(inp, W_ih, b_ih,
                                                W_hh, b_hh, out);
}